// round 6
// baseline (speedup 1.0000x reference)
#include <cuda_runtime.h>
#include <math.h>

#define N_TOT 4096
#define C_DIM 256
#define K_NEG 128
#define HW 1024
#define INV_T (1.0f / 0.07f)
#define Q8 256.0f                        // int8 quant scale for both q and k
#define NEG_SCALE (INV_T / (Q8 * Q8))    // logit scale for int dots
#define NEG_INF (-1e30f)
#define FIX_SCALE 4294967296.0           // 2^32

// Scratch (allocation-free rule: __device__ globals)
__device__ __align__(16) signed char g_qn8[N_TOT * C_DIM]; // q int8*256
__device__ __align__(16) signed char g_kn8[N_TOT * C_DIM]; // k int8*256
__device__ float g_lpos[N_TOT];                             // l_pos logit (fp32)
__device__ unsigned long long g_acc;                        // fixed-point loss sum
__device__ unsigned int       g_done;                       // block completion ctr

__device__ __forceinline__ signed char q8(float v) {
    int iv = __float2int_rn(v * Q8);
    iv = max(-127, min(127, iv));
    return (signed char)iv;
}

// ---------------------------------------------------------------------------
// Kernel 1: normalize q,k over C, transpose [B,C,HW] -> [N,C] int8, and
// compute l_pos = (qn . kn) / T in fp32 while both tiles are resident.
// grid = 512 tiles of 8 positions, block = (8,32).
// ---------------------------------------------------------------------------
__global__ void __launch_bounds__(256) norm_transpose_kernel(
    const float* __restrict__ fq, const float* __restrict__ fk)
{
    if (blockIdx.x == 0 && threadIdx.x == 0 && threadIdx.y == 0)
        g_acc = 0ull;

    const int n0  = blockIdx.x * 8;       // 8 | 1024, tile never crosses batch
    const int b   = n0 / HW;
    const int hw0 = n0 % HW;
    const int tx  = threadIdx.x;          // 0..7  : hw within tile
    const int ty  = threadIdx.y;          // 0..31 : channel group

    __shared__ float tq[C_DIM][9];        // [c][hw], padded
    __shared__ float tk[C_DIM][9];
    __shared__ float ssq[32][8], ssk[32][8], sdt[32][8];
    __shared__ float sinvq[8], sinvk[8];

    const size_t boff = (size_t)b * C_DIM * HW + hw0 + tx;
    const float* bq = fq + boff;
    const float* bk = fk + boff;

    float aq = 0.f, ak = 0.f, ad = 0.f;
    #pragma unroll
    for (int cc = 0; cc < 8; cc++) {      // 8 independent load pairs: MLP=16
        int c = cc * 32 + ty;
        float vq = bq[(size_t)c * HW];    // 32B-sector coalesced across tx
        float vk = bk[(size_t)c * HW];
        tq[c][tx] = vq;
        tk[c][tx] = vk;
        aq += vq * vq;
        ak += vk * vk;
        ad += vq * vk;
    }
    ssq[ty][tx] = aq;
    ssk[ty][tx] = ak;
    sdt[ty][tx] = ad;
    __syncthreads();

    if (ty == 0) {                        // 8 threads finish the reductions
        float sq = 0.f, sk = 0.f, sd = 0.f;
        #pragma unroll
        for (int r = 0; r < 32; r++) {
            sq += ssq[r][tx];
            sk += ssk[r][tx];
            sd += sdt[r][tx];
        }
        float iq = rsqrtf(fmaxf(sq, 1e-24f));   // 1/max(||q||,1e-12)
        float ik = rsqrtf(fmaxf(sk, 1e-24f));
        sinvq[tx] = iq;
        sinvk[tx] = ik;
        g_lpos[n0 + tx] = sd * iq * ik * INV_T; // fp32 positive logit
    }
    __syncthreads();

    const int c = ty * 8 + tx;            // thread owns one channel == linear tid
    #pragma unroll
    for (int r = 0; r < 8; r++) {
        size_t o = (size_t)(n0 + r) * C_DIM + c;
        g_qn8[o] = q8(tq[c][r] * sinvq[r]);
        g_kn8[o] = q8(tk[c][r] * sinvk[r]);
    }
}

// ---------------------------------------------------------------------------
// Kernel 2: per-row gather-dot, int8 dp4a. 2 negatives per warp-LDG (16 lanes
// per 256B row, uint4 each), REDUX half-warp reduce, and EXPLICIT 4-deep load
// batching for MLP (registers idx[4]/kv[4], loads issued before any use).
// ---------------------------------------------------------------------------
__global__ void __launch_bounds__(128, 8) patchnce_main_kernel(
    const int* __restrict__ negs, float* __restrict__ out)
{
    const int n    = blockIdx.x;
    const int tid  = threadIdx.x;
    const int lane = tid & 31;
    const int warp = tid >> 5;
    const int half = lane >> 4;           // 0/1: which negative of the pair
    const int hl   = lane & 15;           // lane within half

    __shared__ uint4 sq8[16];             // q row int8: 256 B
    __shared__ float slog[132];           // 129 logits (0 = l_pos)
    __shared__ float red[4];

    const uint4* __restrict__ k8base = (const uint4*)g_kn8;

    if (tid < 16) sq8[tid] = ((const uint4*)(g_qn8 + (size_t)n * C_DIM))[tid];
    if (tid == 0) slog[0] = g_lpos[n];
    __syncthreads();

    const uint4 qi = sq8[hl];             // channels hl*16 .. hl*16+15 (int8)
    const unsigned m16 = half ? 0xFFFF0000u : 0x0000FFFFu;

    // 32 negatives per warp; indices fetched once, broadcast by shuffle
    int myidx = negs[(size_t)n * K_NEG + warp * 32 + lane];
    myidx += (myidx >= n) ? 1 : 0;        // self-exclusion shift

    #pragma unroll
    for (int j4 = 0; j4 < 16; j4 += 4) {  // 4 warp-LDGs in flight = 8 negatives
        int   idx[4];
        uint4 kv[4];
        #pragma unroll
        for (int u = 0; u < 4; u++)
            idx[u] = __shfl_sync(0xffffffffu, myidx, ((j4 + u) << 1) | half);
        #pragma unroll
        for (int u = 0; u < 4; u++)       // back-to-back independent LDG.128
            kv[u] = __ldg(k8base + (size_t)idx[u] * 16 + hl);
        #pragma unroll
        for (int u = 0; u < 4; u++) {
            int d = __dp4a((int)kv[u].x, (int)qi.x, 0);
            d     = __dp4a((int)kv[u].y, (int)qi.y, d);
            d     = __dp4a((int)kv[u].z, (int)qi.z, d);
            d     = __dp4a((int)kv[u].w, (int)qi.w, d);
            int s = __reduce_add_sync(m16, d);   // 16-lane sum, no smem
            if (hl == 0)
                slog[1 + warp * 32 + ((j4 + u) << 1) + half] =
                    (float)s * NEG_SCALE;
        }
    }
    __syncthreads();

    // logsumexp over 129 logits (thread 0 also covers slog[128])
    const float x     = slog[tid];
    const float extra = (tid == 0) ? slog[128] : NEG_INF;

    float mx = fmaxf(x, extra);
    #pragma unroll
    for (int o = 16; o > 0; o >>= 1)
        mx = fmaxf(mx, __shfl_xor_sync(0xffffffffu, mx, o));
    if (lane == 0) red[warp] = mx;
    __syncthreads();
    mx = fmaxf(fmaxf(red[0], red[1]), fmaxf(red[2], red[3]));
    __syncthreads();                      // WAR on red[]

    float e = expf(x - mx) + ((tid == 0) ? expf(extra - mx) : 0.f);
    #pragma unroll
    for (int o = 16; o > 0; o >>= 1) e += __shfl_xor_sync(0xffffffffu, e, o);
    if (lane == 0) red[warp] = e;
    __syncthreads();

    if (tid == 0) {
        float s = red[0] + red[1] + red[2] + red[3];
        float rowloss = mx + logf(s) - slog[0];   // >= 0 always
        unsigned long long fx =
            (unsigned long long)llrintf(rowloss * (float)FIX_SCALE);
        atomicAdd(&g_acc, fx);            // integer atomics commute: deterministic
        __threadfence();
        unsigned int t = atomicAdd(&g_done, 1u);
        if (t == (unsigned int)(gridDim.x - 1)) {
            unsigned long long total = atomicAdd(&g_acc, 0ull);
            out[0] = (float)((double)total * (1.0 / FIX_SCALE) * (1.0 / N_TOT));
            g_done = 0u;                  // reset for next graph replay
        }
    }
}

// ---------------------------------------------------------------------------
extern "C" void kernel_launch(void* const* d_in, const int* in_sizes, int n_in,
                              void* d_out, int out_size)
{
    const float* fq   = (const float*)d_in[0];
    const float* fk   = (const float*)d_in[1];
    const int*   negs = (const int*)d_in[2];
    float*       out  = (float*)d_out;

    norm_transpose_kernel<<<512, dim3(8, 32)>>>(fq, fk);
    patchnce_main_kernel<<<N_TOT, 128>>>(negs, out);
}